// round 1
// baseline (speedup 1.0000x reference)
#include <cuda_runtime.h>
#include <cuda_bf16.h>

// Problem: out = sum_i | cumsum(x0 - x1)_i |, x = d_in[0] as (2, N) fp32, N = 2^23.
// Two-pass scan:
//   pass1: per-warp (1024-elem segment) sums of (x0-x1), fp64
//   pass2: exclusive scan of 8192 warp sums (one block)
//   pass3: per-warp tile scan (shuffle) + carry, accumulate sum|cdf|, atomicAdd(double)
//   pass4: write fp32 scalar

#define SEG        1024          // elements per warp segment
#define WPB        8             // warps per block
#define TPB        256
#define MAX_WARPS  8192          // N / SEG for N = 2^23

__device__ double g_warpSums[MAX_WARPS];
__device__ double g_warpOffsets[MAX_WARPS];
__device__ double g_acc;

__global__ void __launch_bounds__(TPB) emd_pass1(const float* __restrict__ x, int N) {
    const float4* x0 = (const float4*)x;
    const float4* x1 = (const float4*)(x + N);
    int wid  = threadIdx.x >> 5;
    int lane = threadIdx.x & 31;
    int gw   = blockIdx.x * WPB + wid;
    long base4 = (long)gw * (SEG / 4);

    double s = 0.0;
#pragma unroll
    for (int it = 0; it < SEG / 128; ++it) {
        float4 a = x0[base4 + it * 32 + lane];
        float4 b = x1[base4 + it * 32 + lane];
        s += (double)(a.x - b.x) + (double)(a.y - b.y)
           + (double)(a.z - b.z) + (double)(a.w - b.w);
    }
#pragma unroll
    for (int off = 16; off; off >>= 1)
        s += __shfl_down_sync(0xffffffffu, s, off);
    if (lane == 0) g_warpSums[gw] = s;
}

// One block of 1024 threads; each thread owns 8 consecutive warp sums.
__global__ void __launch_bounds__(1024) emd_pass2() {
    __shared__ double sh[1024];
    int t = threadIdx.x;

    double l[8];
    double run = 0.0;
#pragma unroll
    for (int j = 0; j < 8; ++j) {
        run += g_warpSums[t * 8 + j];
        l[j] = run;
    }
    sh[t] = run;
    __syncthreads();

    for (int off = 1; off < 1024; off <<= 1) {
        double v = (t >= off) ? sh[t - off] : 0.0;
        __syncthreads();
        sh[t] += v;
        __syncthreads();
    }

    double excl = sh[t] - run;   // exclusive prefix of this thread's chunk
#pragma unroll
    for (int j = 0; j < 8; ++j)
        g_warpOffsets[t * 8 + j] = excl + (j ? l[j - 1] : 0.0);

    if (t == 0) g_acc = 0.0;
}

__global__ void __launch_bounds__(TPB) emd_pass3(const float* __restrict__ x, int N) {
    const float4* x0 = (const float4*)x;
    const float4* x1 = (const float4*)(x + N);
    int wid  = threadIdx.x >> 5;
    int lane = threadIdx.x & 31;
    int gw   = blockIdx.x * WPB + wid;
    long base4 = (long)gw * (SEG / 4);

    double carry = g_warpOffsets[gw];
    double acc   = 0.0;

#pragma unroll
    for (int it = 0; it < SEG / 128; ++it) {
        float4 a = x0[base4 + it * 32 + lane];
        float4 b = x1[base4 + it * 32 + lane];
        double s0 = (double)(a.x - b.x);
        double s1 = s0 + (double)(a.y - b.y);
        double s2 = s1 + (double)(a.z - b.z);
        double s3 = s2 + (double)(a.w - b.w);

        // warp inclusive scan of lane totals
        double v = s3;
#pragma unroll
        for (int off = 1; off < 32; off <<= 1) {
            double n = __shfl_up_sync(0xffffffffu, v, off);
            if (lane >= off) v += n;
        }
        double base = carry + v - s3;   // exclusive prefix for this lane
        acc += fabs(base + s0) + fabs(base + s1)
             + fabs(base + s2) + fabs(base + s3);
        carry += __shfl_sync(0xffffffffu, v, 31);
    }

#pragma unroll
    for (int off = 16; off; off >>= 1)
        acc += __shfl_down_sync(0xffffffffu, acc, off);
    if (lane == 0) atomicAdd(&g_acc, acc);
}

__global__ void emd_pass4(float* __restrict__ out) {
    out[0] = (float)g_acc;
}

extern "C" void kernel_launch(void* const* d_in, const int* in_sizes, int n_in,
                              void* d_out, int out_size) {
    const float* x = (const float*)d_in[0];
    int N = in_sizes[0] / 2;                 // 8388608
    int nwarps  = N / SEG;                   // 8192
    int nblocks = nwarps / WPB;              // 1024

    emd_pass1<<<nblocks, TPB>>>(x, N);
    emd_pass2<<<1, 1024>>>();
    emd_pass3<<<nblocks, TPB>>>(x, N);
    emd_pass4<<<1, 1>>>((float*)d_out);
}

// round 2
// speedup vs baseline: 3.5041x; 3.5041x over previous
#include <cuda_runtime.h>
#include <cuda_bf16.h>

// out = sum_i | cumsum(x0 - x1)_i |, x = d_in[0] as (2, N) fp32, N = 2^23.
// All hot-loop math fp32 (reference also computes cumsum in fp32).
//   pass1: per-warp (1024-elem segment) sums of (x0-x1), fp32 -> g_warpSums
//   pass2: one block: exclusive scan of 8192 warp sums in fp64 -> g_warpOffsets (fp32)
//   pass3: per-warp: 2 tile-scans of 512 elems (16/lane in regs), fp32 shuffle scan,
//          accumulate sum|cdf| per warp -> g_partials (no atomics)
//   pass4: one block: fp64 reduce of 8192 partials -> fp32 scalar

#define SEG        1024
#define WPB        8
#define TPB        256
#define MAX_WARPS  8192

__device__ float g_warpSums[MAX_WARPS];
__device__ float g_warpOffsets[MAX_WARPS];
__device__ float g_partials[MAX_WARPS];

__global__ void __launch_bounds__(TPB) emd_pass1(const float* __restrict__ x, int N) {
    const float4* x0 = (const float4*)x;
    const float4* x1 = (const float4*)(x + N);
    int wid  = threadIdx.x >> 5;
    int lane = threadIdx.x & 31;
    int gw   = blockIdx.x * WPB + wid;
    long base4 = (long)gw * (SEG / 4);

    float s = 0.f;
#pragma unroll
    for (int it = 0; it < SEG / 128; ++it) {
        float4 a = x0[base4 + it * 32 + lane];
        float4 b = x1[base4 + it * 32 + lane];
        s += (a.x - b.x) + (a.y - b.y) + (a.z - b.z) + (a.w - b.w);
    }
#pragma unroll
    for (int off = 16; off; off >>= 1)
        s += __shfl_down_sync(0xffffffffu, s, off);
    if (lane == 0) g_warpSums[gw] = s;
}

// One block, 1024 threads; each thread owns 8 consecutive warp sums. fp64 internally.
__global__ void __launch_bounds__(1024) emd_pass2() {
    __shared__ double sh[1024];
    int t = threadIdx.x;

    double l[8];
    double run = 0.0;
#pragma unroll
    for (int j = 0; j < 8; ++j) {
        run += (double)g_warpSums[t * 8 + j];
        l[j] = run;
    }
    sh[t] = run;
    __syncthreads();

    for (int off = 1; off < 1024; off <<= 1) {
        double v = (t >= off) ? sh[t - off] : 0.0;
        __syncthreads();
        sh[t] += v;
        __syncthreads();
    }

    double excl = sh[t] - run;
#pragma unroll
    for (int j = 0; j < 8; ++j)
        g_warpOffsets[t * 8 + j] = (float)(excl + (j ? l[j - 1] : 0.0));
}

// Each warp: SEG=1024 elems as 2 tiles of 512; each lane owns 16 contiguous elems.
__global__ void __launch_bounds__(TPB) emd_pass3(const float* __restrict__ x, int N) {
    const float4* x0 = (const float4*)x;
    const float4* x1 = (const float4*)(x + N);
    int wid  = threadIdx.x >> 5;
    int lane = threadIdx.x & 31;
    int gw   = blockIdx.x * WPB + wid;

    float carry = g_warpOffsets[gw];
    float acc   = 0.f;

#pragma unroll
    for (int tile = 0; tile < 2; ++tile) {
        // lane-owned 16 contiguous elements: float4 index = segbase4 + tile*128 + lane*4 + j
        long b4 = (long)gw * (SEG / 4) + tile * 128 + lane * 4;

        float d[16];
#pragma unroll
        for (int j = 0; j < 4; ++j) {
            float4 a = x0[b4 + j];
            float4 b = x1[b4 + j];
            d[j * 4 + 0] = a.x - b.x;
            d[j * 4 + 1] = a.y - b.y;
            d[j * 4 + 2] = a.z - b.z;
            d[j * 4 + 3] = a.w - b.w;
        }

        // in-register inclusive prefix over the 16 lane-local elements
#pragma unroll
        for (int j = 1; j < 16; ++j) d[j] += d[j - 1];

        // warp inclusive scan of lane totals (fp32)
        float tot = d[15];
        float v = tot;
#pragma unroll
        for (int off = 1; off < 32; off <<= 1) {
            float n = __shfl_up_sync(0xffffffffu, v, off);
            if (lane >= off) v += n;
        }
        float base = carry + (v - tot);   // exclusive prefix for this lane
#pragma unroll
        for (int j = 0; j < 16; ++j)
            acc += fabsf(base + d[j]);
        carry += __shfl_sync(0xffffffffu, v, 31);
    }

#pragma unroll
    for (int off = 16; off; off >>= 1)
        acc += __shfl_down_sync(0xffffffffu, acc, off);
    if (lane == 0) g_partials[gw] = acc;
}

// One block, 1024 threads: fp64 reduce of 8192 partials.
__global__ void __launch_bounds__(1024) emd_pass4(float* __restrict__ out) {
    __shared__ double sh[1024];
    int t = threadIdx.x;
    double s = (double)g_partials[t] + (double)g_partials[t + 1024]
             + (double)g_partials[t + 2048] + (double)g_partials[t + 3072]
             + (double)g_partials[t + 4096] + (double)g_partials[t + 5120]
             + (double)g_partials[t + 6144] + (double)g_partials[t + 7168];
    sh[t] = s;
    __syncthreads();
    for (int off = 512; off; off >>= 1) {
        if (t < off) sh[t] += sh[t + off];
        __syncthreads();
    }
    if (t == 0) out[0] = (float)sh[0];
}

extern "C" void kernel_launch(void* const* d_in, const int* in_sizes, int n_in,
                              void* d_out, int out_size) {
    const float* x = (const float*)d_in[0];
    int N = in_sizes[0] / 2;                 // 8388608
    int nwarps  = N / SEG;                   // 8192
    int nblocks = nwarps / WPB;              // 1024

    emd_pass1<<<nblocks, TPB>>>(x, N);
    emd_pass2<<<1, 1024>>>();
    emd_pass3<<<nblocks, TPB>>>(x, N);
    emd_pass4<<<1, 1024>>>((float*)d_out);
}

// round 3
// speedup vs baseline: 7.9133x; 2.2583x over previous
#include <cuda_runtime.h>
#include <cuda_bf16.h>

// out = sum_i | cumsum(x0 - x1)_i |, x = d_in[0] as (2, N) fp32, N = 2^23.
// Single persistent kernel, grid = 148 blocks (1/SM, co-resident), 1024 threads.
//   Phase A: load chunk once from DRAM, diff -> dynamic smem, block sum.
//   Grid sync (self-resetting double-counter protocol, graph-replay safe).
//   Phase B: block/warp prefix + per-tile warp shuffle scans from smem, sum|cdf|.
//   Grid sync 2, block 0 reduces partials (fp64) -> fp32 scalar.

#define GRID_N   148
#define TPB      1024
#define NWARP    32
#define BLK_F4   14336            // float4 per full block (57344 elems, 224 KB smem)
#define WARP_F4  448              // float4 per warp
#define LANE_J   14               // float4 per lane (tiles per warp)

__device__ float    g_blockSums[GRID_N];
__device__ float    g_blockPartials[GRID_N];
__device__ unsigned g_ctrA;       // zero-initialized at module load
__device__ unsigned g_ctrB;

// Grid-wide sync on `ctr`; last arriver resets `other` before releasing.
// Invariant across graph replays: each counter is reset at the *other* sync
// point, after all blocks are provably past the spin that reads it.
__device__ __forceinline__ void grid_sync(unsigned* ctr, unsigned* other) {
    __syncthreads();
    if (threadIdx.x == 0) {
        __threadfence();                      // publish this block's globals
        unsigned v = atomicAdd(ctr, 1u);
        if (v == GRID_N - 1) {                // last arriver
            *other = 0u;
            __threadfence();
            atomicAdd(ctr, 1u);               // release: ctr -> GRID_N + 1
        }
        while (*(volatile unsigned*)ctr < GRID_N + 1u) { }
        __threadfence();                      // acquire others' globals
    }
    __syncthreads();
}

__global__ void __launch_bounds__(TPB) emd_fused(const float* __restrict__ x,
                                                 float* __restrict__ out, int N) {
    extern __shared__ float4 sdiff[];         // BLK_F4 float4
    __shared__ float sWarpSums[NWARP];
    __shared__ float sWarpAcc[NWARP];
    __shared__ float sBlockPrefix;

    const int  tid  = threadIdx.x;
    const int  w    = tid >> 5;
    const int  lane = tid & 31;
    const int  bid  = blockIdx.x;
    const long tot4 = (long)N / 4;            // 2^21 float4

    const float4* x0 = (const float4*)x;
    const float4* x1 = (const float4*)(x + N);

    const long blockStart4 = (long)bid * BLK_F4;
    const int  warpLocal4  = w * WARP_F4;

    // ---------------- Phase A: DRAM -> smem diffs + block sum ----------------
    float s = 0.f;
#pragma unroll
    for (int j = 0; j < LANE_J; ++j) {
        long t4 = blockStart4 + warpLocal4 + j * 32 + lane;
        if (t4 < tot4) {
            float4 a = x0[t4];
            float4 b = x1[t4];
            float4 d;
            d.x = a.x - b.x; d.y = a.y - b.y; d.z = a.z - b.z; d.w = a.w - b.w;
            sdiff[warpLocal4 + j * 32 + lane] = d;
            s += (d.x + d.y) + (d.z + d.w);
        }
    }
#pragma unroll
    for (int off = 16; off; off >>= 1)
        s += __shfl_down_sync(0xffffffffu, s, off);
    if (lane == 0) sWarpSums[w] = s;
    __syncthreads();
    if (tid == 0) {
        float bs = 0.f;
#pragma unroll
        for (int i = 0; i < NWARP; ++i) bs += sWarpSums[i];
        g_blockSums[bid] = bs;
    }

    grid_sync(&g_ctrA, &g_ctrB);

    // ---------------- Phase B: prefixes + scan from smem ----------------
    if (w == 0) {                             // block prefix over preceding blocks
        float p = 0.f;
#pragma unroll
        for (int i = lane; i < GRID_N; i += 32)
            if (i < bid) p += g_blockSums[i];
#pragma unroll
        for (int off = 16; off; off >>= 1)
            p += __shfl_down_sync(0xffffffffu, p, off);
        if (lane == 0) sBlockPrefix = p;
    }
    __syncthreads();

    float carry = sBlockPrefix;
    for (int i = 0; i < w; ++i) carry += sWarpSums[i];   // warp prefix in block

    float acc = 0.f;
#pragma unroll
    for (int j = 0; j < LANE_J; ++j) {
        long tile4 = blockStart4 + warpLocal4 + j * 32;
        if (tile4 < tot4) {
            float4 d = sdiff[warpLocal4 + j * 32 + lane]; // 32 consecutive f4: conflict-free
            float s0 = d.x;
            float s1 = s0 + d.y;
            float s2 = s1 + d.z;
            float s3 = s2 + d.w;

            float v = s3;                                  // warp inclusive scan
#pragma unroll
            for (int off = 1; off < 32; off <<= 1) {
                float n = __shfl_up_sync(0xffffffffu, v, off);
                if (lane >= off) v += n;
            }
            float base = carry + (v - s3);                 // lane-exclusive prefix
            acc += fabsf(base + s0) + fabsf(base + s1)
                 + fabsf(base + s2) + fabsf(base + s3);
            carry += __shfl_sync(0xffffffffu, v, 31);
        }
    }
#pragma unroll
    for (int off = 16; off; off >>= 1)
        acc += __shfl_down_sync(0xffffffffu, acc, off);
    if (lane == 0) sWarpAcc[w] = acc;
    __syncthreads();
    if (tid == 0) {
        float bp = 0.f;
#pragma unroll
        for (int i = 0; i < NWARP; ++i) bp += sWarpAcc[i];
        g_blockPartials[bid] = bp;
    }

    grid_sync(&g_ctrB, &g_ctrA);

    // ---------------- Final: block 0 reduces 148 partials ----------------
    if (bid == 0 && w == 0) {
        double p = 0.0;
#pragma unroll
        for (int i = lane; i < GRID_N; i += 32)
            p += (double)g_blockPartials[i];
#pragma unroll
        for (int off = 16; off; off >>= 1)
            p += __shfl_down_sync(0xffffffffu, p, off);
        if (lane == 0) out[0] = (float)p;
    }
}

extern "C" void kernel_launch(void* const* d_in, const int* in_sizes, int n_in,
                              void* d_out, int out_size) {
    const float* x = (const float*)d_in[0];
    int N = in_sizes[0] / 2;                  // 8388608
    size_t smem = (size_t)BLK_F4 * sizeof(float4);   // 229376 B

    static bool attr_done = false;            // host-side, deterministic
    if (!attr_done) {
        cudaFuncSetAttribute(emd_fused,
                             cudaFuncAttributeMaxDynamicSharedMemorySize,
                             (int)smem);
        attr_done = true;
    }
    emd_fused<<<GRID_N, TPB, smem>>>(x, (float*)d_out, N);
}

// round 4
// speedup vs baseline: 7.9265x; 1.0017x over previous
#include <cuda_runtime.h>
#include <cuda_bf16.h>

// out = sum_i | cumsum(x0 - x1)_i |, x = d_in[0] as (2, N) fp32, N = 2^23.
// Single persistent kernel, grid = 148 blocks (1/SM), 1024 threads.
//   Phase A: batched LDG.128 (MLP 8/warp) -> diffs in dynamic smem, block sum.
//   Grid sync (self-resetting double-counter, graph-replay safe).
//   Phase B: block/warp prefix + pipelined per-tile warp shuffle scans, sum|cdf|.
//   Grid sync 2, block 0 reduces partials (fp64) -> fp32 scalar.

#define GRID_N   148
#define TPB      1024
#define NWARP    32
#define BLK_F4   14336            // float4 per block (57344 elems, 224 KB smem)
#define WARP_F4  448              // float4 per warp
#define LANE_J   14               // tiles per warp (float4 per lane)

__device__ float    g_blockSums[GRID_N];
__device__ float    g_blockPartials[GRID_N];
__device__ unsigned g_ctrA;       // zero-initialized at module load
__device__ unsigned g_ctrB;

__device__ __forceinline__ void grid_sync(unsigned* ctr, unsigned* other) {
    __syncthreads();
    if (threadIdx.x == 0) {
        __threadfence();
        unsigned v = atomicAdd(ctr, 1u);
        if (v == GRID_N - 1) {
            *other = 0u;
            __threadfence();
            atomicAdd(ctr, 1u);               // release: ctr -> GRID_N + 1
        }
        while (*(volatile unsigned*)ctr < GRID_N + 1u) { }
        __threadfence();
    }
    __syncthreads();
}

__global__ void __launch_bounds__(TPB) emd_fused(const float* __restrict__ x,
                                                 float* __restrict__ out, int N) {
    extern __shared__ float4 sdiff[];         // BLK_F4 float4
    __shared__ float sWarpSums[NWARP];
    __shared__ float sWarpAcc[NWARP];
    __shared__ float sBlockPrefix;

    const int  tid  = threadIdx.x;
    const int  w    = tid >> 5;
    const int  lane = tid & 31;
    const int  bid  = blockIdx.x;
    const long tot4 = (long)N / 4;            // 2^21 float4

    const float4* x0 = (const float4*)x;
    const float4* x1 = (const float4*)(x + N);

    const long blockStart4 = (long)bid * BLK_F4;
    const int  warpLocal4  = w * WARP_F4;
    const float4 z4 = make_float4(0.f, 0.f, 0.f, 0.f);

    // ---------------- Phase A: batched loads -> smem diffs + block sum ----------------
    float s = 0.f;
#pragma unroll
    for (int g = 0; g < 4; ++g) {             // groups: 4,4,4,2 tiles
        const int gt = (g < 3) ? 4 : 2;
        float4 a[4], b[4];
#pragma unroll
        for (int u = 0; u < 4; ++u) {
            if (u < gt) {
                long t4 = blockStart4 + warpLocal4 + (g * 4 + u) * 32 + lane;
                bool ok = t4 < tot4;
                a[u] = ok ? x0[t4] : z4;
                b[u] = ok ? x1[t4] : z4;
            }
        }
#pragma unroll
        for (int u = 0; u < 4; ++u) {
            if (u < gt) {
                float4 d;
                d.x = a[u].x - b[u].x; d.y = a[u].y - b[u].y;
                d.z = a[u].z - b[u].z; d.w = a[u].w - b[u].w;
                sdiff[warpLocal4 + (g * 4 + u) * 32 + lane] = d;
                s += (d.x + d.y) + (d.z + d.w);
            }
        }
    }
#pragma unroll
    for (int off = 16; off; off >>= 1)
        s += __shfl_down_sync(0xffffffffu, s, off);
    if (lane == 0) sWarpSums[w] = s;
    __syncthreads();
    if (tid == 0) {
        float bs = 0.f;
#pragma unroll
        for (int i = 0; i < NWARP; ++i) bs += sWarpSums[i];
        g_blockSums[bid] = bs;
    }

    grid_sync(&g_ctrA, &g_ctrB);

    // ---------------- Phase B: prefixes + pipelined tile scans ----------------
    if (w == 0) {
        float p = 0.f;
#pragma unroll
        for (int i = lane; i < GRID_N; i += 32)
            if (i < bid) p += g_blockSums[i];
#pragma unroll
        for (int off = 16; off; off >>= 1)
            p += __shfl_down_sync(0xffffffffu, p, off);
        if (lane == 0) sBlockPrefix = p;
    }
    __syncthreads();

    float carry = sBlockPrefix;
    for (int i = 0; i < w; ++i) carry += sWarpSums[i];

    float acc = 0.f;
    float4 dc = sdiff[warpLocal4 + lane];      // prefetch tile 0
#pragma unroll
    for (int j = 0; j < LANE_J; ++j) {
        float4 dn = (j + 1 < LANE_J) ? sdiff[warpLocal4 + (j + 1) * 32 + lane] : dc;

        float s0 = dc.x;
        float s1 = s0 + dc.y;
        float s2 = s1 + dc.z;
        float s3 = s2 + dc.w;

        float v = s3;                          // warp inclusive scan of lane totals
#pragma unroll
        for (int off = 1; off < 32; off <<= 1) {
            float n = __shfl_up_sync(0xffffffffu, v, off);
            if (lane >= off) v += n;
        }
        float base = carry + (v - s3);
        acc += fabsf(base + s0) + fabsf(base + s1)
             + fabsf(base + s2) + fabsf(base + s3);
        carry += __shfl_sync(0xffffffffu, v, 31);
        dc = dn;
    }

#pragma unroll
    for (int off = 16; off; off >>= 1)
        acc += __shfl_down_sync(0xffffffffu, acc, off);
    if (lane == 0) sWarpAcc[w] = acc;
    __syncthreads();
    if (tid == 0) {
        float bp = 0.f;
#pragma unroll
        for (int i = 0; i < NWARP; ++i) bp += sWarpAcc[i];
        g_blockPartials[bid] = bp;
    }

    grid_sync(&g_ctrB, &g_ctrA);

    // ---------------- Final: block 0 reduces 148 partials (fp64) ----------------
    if (bid == 0 && w == 0) {
        double p = 0.0;
#pragma unroll
        for (int i = lane; i < GRID_N; i += 32)
            p += (double)g_blockPartials[i];
#pragma unroll
        for (int off = 16; off; off >>= 1)
            p += __shfl_down_sync(0xffffffffu, p, off);
        if (lane == 0) out[0] = (float)p;
    }
}

extern "C" void kernel_launch(void* const* d_in, const int* in_sizes, int n_in,
                              void* d_out, int out_size) {
    const float* x = (const float*)d_in[0];
    int N = in_sizes[0] / 2;                  // 8388608
    size_t smem = (size_t)BLK_F4 * sizeof(float4);   // 229376 B

    static bool attr_done = false;
    if (!attr_done) {
        cudaFuncSetAttribute(emd_fused,
                             cudaFuncAttributeMaxDynamicSharedMemorySize,
                             (int)smem);
        attr_done = true;
    }
    emd_fused<<<GRID_N, TPB, smem>>>(x, (float*)d_out, N);
}